// round 6
// baseline (speedup 1.0000x reference)
#include <cuda_runtime.h>
#include <cuda_bf16.h>
#include <cstdint>

#define NN 50000
#define NE 800000
#define NG 64
#define HID 300
#define HID2 600
#define NLAYER 5
#define EPSV 1e-5f

// ======================= scratch =======================
__device__ float g_hraw[(size_t)NN * HID];
__device__ float g_agg [(size_t)NN * HID];
__device__ float g_t   [(size_t)NN * HID2];
__device__ int   g_deg [NN];
__device__ int   g_rowptr[NN + 1];
__device__ int   g_cursor[NN];
__device__ int   g_srcs[NE];
__device__ float g_ews [NE];
__device__ float g_sum1[HID2], g_sq1[HID2], g_a1[HID2], g_c1[HID2];
__device__ float g_sum2[HID],  g_sq2[HID],  g_a2[HID],  g_c2[HID];

// ======================= PTX helpers (non-'a' features only) =======================
__device__ __forceinline__ uint32_t smem_u32(const void* p) {
    uint32_t a;
    asm("{ .reg .u64 t; cvta.to.shared.u64 t, %1; cvt.u32.u64 %0, t; }" : "=r"(a) : "l"(p));
    return a;
}
__device__ __forceinline__ void ldsm_x4(uint32_t* r, uint32_t addr) {
    asm volatile("ldmatrix.sync.aligned.m8n8.x4.shared.b16 {%0,%1,%2,%3}, [%4];"
        : "=r"(r[0]), "=r"(r[1]), "=r"(r[2]), "=r"(r[3]) : "r"(addr));
}
__device__ __forceinline__ void ldsm_x4_t(uint32_t* r, uint32_t addr) {
    asm volatile("ldmatrix.sync.aligned.m8n8.x4.trans.shared.b16 {%0,%1,%2,%3}, [%4];"
        : "=r"(r[0]), "=r"(r[1]), "=r"(r[2]), "=r"(r[3]) : "r"(addr));
}
__device__ __forceinline__ void mma_bf16(float* d, const uint32_t* a, uint32_t b0, uint32_t b1) {
    asm volatile(
        "mma.sync.aligned.m16n8k16.row.col.f32.bf16.bf16.f32 "
        "{%0,%1,%2,%3}, {%4,%5,%6,%7}, {%8,%9}, {%0,%1,%2,%3};"
        : "+f"(d[0]), "+f"(d[1]), "+f"(d[2]), "+f"(d[3])
        : "r"(a[0]), "r"(a[1]), "r"(a[2]), "r"(a[3]), "r"(b0), "r"(b1));
}
// split-2 bf16: v = hi + lo
__device__ __forceinline__ void bf16_split(float v, uint16_t& hi, uint16_t& lo) {
    __nv_bfloat16 h = __float2bfloat16(v);
    __nv_bfloat16 l = __float2bfloat16(v - __bfloat162float(h));
    hi = __bfloat16_as_ushort(h);
    lo = __bfloat16_as_ushort(l);
}
#define SWZ_A(off) ((off) ^ (((off) >> 3) & 0x70))   // 128B rows: row%8 -> chunk bits
#define SWZ_B(off) ((off) ^ (((off) >> 4) & 0x70))   // 256B rows: row%8 -> chunk bits

// ======================= utility kernels =======================
__global__ void k_zero_f(float* p, int n) {
    int i = blockIdx.x * blockDim.x + threadIdx.x;
    if (i < n) p[i] = 0.f;
}
__global__ void k_zero_deg() {
    int i = blockIdx.x * blockDim.x + threadIdx.x;
    if (i < NN) g_deg[i] = 0;
}
__global__ void k_count(const int* __restrict__ dst) {
    int e = blockIdx.x * blockDim.x + threadIdx.x;
    if (e < NE) atomicAdd(&g_deg[dst[e]], 1);
}
__global__ void k_scan() {
    __shared__ int sh[1024];
    int offset = 0;
    for (int base = 0; base < NN; base += 1024) {
        int i = base + threadIdx.x;
        int v = (i < NN) ? g_deg[i] : 0;
        sh[threadIdx.x] = v;
        __syncthreads();
        #pragma unroll
        for (int d = 1; d < 1024; d <<= 1) {
            int t = (threadIdx.x >= d) ? sh[threadIdx.x - d] : 0;
            __syncthreads();
            sh[threadIdx.x] += t;
            __syncthreads();
        }
        int incl = sh[threadIdx.x];
        if (i < NN) {
            g_rowptr[i] = offset + incl - v;
            g_cursor[i] = offset + incl - v;
        }
        offset += sh[1023];
        __syncthreads();
    }
    if (threadIdx.x == 0) g_rowptr[NN] = offset;
}
__global__ void k_scatter(const int* __restrict__ src, const int* __restrict__ dst,
                          const float* __restrict__ ea) {
    int e = blockIdx.x * blockDim.x + threadIdx.x;
    if (e < NE) {
        int d = dst[e];
        int p = atomicAdd(&g_cursor[d], 1);
        g_srcs[p] = src[e];
        g_ews[p]  = ea[e];
    }
}

// ======================= SpMM (gather + segment-sum) =======================
template <bool TRANS>
__global__ void k_spmm(const float* __restrict__ hraw,
                       const float* __restrict__ a, const float* __restrict__ c) {
    int n = blockIdx.x;
    int f = threadIdx.x;
    int beg = g_rowptr[n], end = g_rowptr[n + 1];
    if (f >= HID) return;
    float af = 0.f, cf = 0.f;
    if (TRANS) { af = a[f]; cf = c[f]; }
    float acc = 0.f;
    for (int e = beg; e < end; e++) {
        int s  = g_srcs[e];
        float w = g_ews[e];
        float v = __ldg(hraw + (size_t)s * HID + f);
        if (TRANS) v = fmaxf(fmaf(af, v, cf), 0.f);
        acc = fmaf(w, v, acc);
    }
    g_agg[(size_t)n * HID + f] = acc;
}

// ======================= SIMT GEMM for tiny lin0 (K=20) =======================
__global__ __launch_bounds__(256, 2)
void k_gemm0(const float* __restrict__ A, const float* __restrict__ B,
             const float* __restrict__ bias, float* __restrict__ C,
             int M, int N, int K) {
    __shared__ float As[8][132];
    __shared__ float Bs[8][128];
    int tid = threadIdx.x;
    int tx = tid & 15, ty = tid >> 4;
    int m0 = blockIdx.y * 128, n0 = blockIdx.x * 128;
    int arow = tid >> 1, ak = (tid & 1) * 4;
    int bk = tid >> 5, bn = (tid & 31) * 4;
    float acc[8][8];
    #pragma unroll
    for (int i = 0; i < 8; i++)
        #pragma unroll
        for (int j = 0; j < 8; j++) acc[i][j] = 0.f;
    for (int k0 = 0; k0 < K; k0 += 8) {
        float4 av = make_float4(0.f, 0.f, 0.f, 0.f);
        if (m0 + arow < M && k0 + ak < K)
            av = *(const float4*)(A + (size_t)(m0 + arow) * K + k0 + ak);
        As[ak + 0][arow] = av.x; As[ak + 1][arow] = av.y;
        As[ak + 2][arow] = av.z; As[ak + 3][arow] = av.w;
        float4 bv = make_float4(0.f, 0.f, 0.f, 0.f);
        if (k0 + bk < K && n0 + bn < N)
            bv = *(const float4*)(B + (size_t)(k0 + bk) * N + n0 + bn);
        *(float4*)&Bs[bk][bn] = bv;
        __syncthreads();
        #pragma unroll
        for (int kk = 0; kk < 8; kk++) {
            float a[8], b[8];
            #pragma unroll
            for (int i = 0; i < 8; i++) a[i] = As[kk][ty * 8 + i];
            #pragma unroll
            for (int j = 0; j < 8; j++) b[j] = Bs[kk][tx * 8 + j];
            #pragma unroll
            for (int i = 0; i < 8; i++)
                #pragma unroll
                for (int j = 0; j < 8; j++) acc[i][j] = fmaf(a[i], b[j], acc[i][j]);
        }
        __syncthreads();
    }
    #pragma unroll
    for (int i = 0; i < 8; i++) {
        int row = m0 + ty * 8 + i;
        if (row < M) {
            #pragma unroll
            for (int j = 0; j < 8; j += 4) {
                int col = n0 + tx * 8 + j;
                if (col < N) {
                    float4 o = make_float4(acc[i][j] + bias[col], acc[i][j+1] + bias[col+1],
                                           acc[i][j+2] + bias[col+2], acc[i][j+3] + bias[col+3]);
                    *(float4*)(C + (size_t)row * N + col) = o;
                }
            }
        }
    }
}

// ======================= mma.sync bf16 split-2 GEMM =======================
// C[M,N] = f(A)[M,K] @ B[K,N] + bias;  f = TRANS ? relu(ta[k]*v+tc[k]) : id
// Tile 128x128x32. 8 warps: wm = w&1 (M 2x64), wn = w>>1 (N 4x32).
// As: [128 rows][64 bf16] (cols 0-31 hi, 32-63 lo), 128B/row, swizzled.
// Bh/Bl: [32 k][128 n] bf16, 256B/row, swizzled. B-frags via ldmatrix.x4.trans.
template <bool TRANS>
__global__ __launch_bounds__(256, 2)
void k_tgemm(const float* __restrict__ A, const float* __restrict__ B,
             const float* __restrict__ bias,
             const float* __restrict__ ta, const float* __restrict__ tc,
             float* __restrict__ C, int M, int N, int K) {
    __shared__ uint16_t As[128 * 64];
    __shared__ uint16_t Bh[32 * 128];
    __shared__ uint16_t Bl[32 * 128];
    const uint32_t sA = smem_u32(As);
    const uint32_t sBh = smem_u32(Bh);
    const uint32_t sBl = smem_u32(Bl);

    const int tid  = threadIdx.x;
    const int lane = tid & 31;
    const int w    = tid >> 5;
    const int wm   = w & 1;
    const int wn   = w >> 1;
    const int m0 = blockIdx.y * 128;
    const int n0 = blockIdx.x * 128;

    // A loader: row = tid>>1 (128 rows), k-offset = (tid&1)*16 + q*4
    const int la_row = tid >> 1;
    const int la_k0  = (tid & 1) << 4;
    const bool la_rowv = (m0 + la_row) < M;
    const float* Arow = A + (size_t)(m0 + la_row) * K;
    // B loader: k row = tid>>3 (32 rows), n-offset = (tid&7)*16 + q*4
    const int lb_k = tid >> 3;
    const int lb_n0 = (tid & 7) << 4;

    float d[4][4][4];
    #pragma unroll
    for (int mi = 0; mi < 4; mi++)
        #pragma unroll
        for (int ni = 0; ni < 4; ni++)
            #pragma unroll
            for (int e = 0; e < 4; e++) d[mi][ni][e] = 0.f;

    const int nK = (K + 31) / 32;
    for (int t = 0; t < nK; t++) {
        const int kt = t * 32;
        // ---- load A chunk: 128 x 32 fp32 -> transform -> split -> As ----
        #pragma unroll
        for (int q = 0; q < 4; q++) {
            int kl = la_k0 + q * 4;
            int gk = kt + kl;
            float4 v = make_float4(0.f, 0.f, 0.f, 0.f);
            if (la_rowv) {
                if (gk + 3 < K) v = *(const float4*)(Arow + gk);
                else {
                    if (gk + 0 < K) v.x = Arow[gk + 0];
                    if (gk + 1 < K) v.y = Arow[gk + 1];
                    if (gk + 2 < K) v.z = Arow[gk + 2];
                    if (gk + 3 < K) v.w = Arow[gk + 3];
                }
                if (TRANS) {
                    if (gk + 0 < K) v.x = fmaxf(fmaf(ta[gk + 0], v.x, tc[gk + 0]), 0.f);
                    if (gk + 1 < K) v.y = fmaxf(fmaf(ta[gk + 1], v.y, tc[gk + 1]), 0.f);
                    if (gk + 2 < K) v.z = fmaxf(fmaf(ta[gk + 2], v.z, tc[gk + 2]), 0.f);
                    if (gk + 3 < K) v.w = fmaxf(fmaf(ta[gk + 3], v.w, tc[gk + 3]), 0.f);
                }
            }
            uint16_t h0, l0, h1, l1, h2, l2, h3, l3;
            bf16_split(v.x, h0, l0); bf16_split(v.y, h1, l1);
            bf16_split(v.z, h2, l2); bf16_split(v.w, h3, l3);
            uint2 hv, lv;
            hv.x = (uint32_t)h0 | ((uint32_t)h1 << 16);
            hv.y = (uint32_t)h2 | ((uint32_t)h3 << 16);
            lv.x = (uint32_t)l0 | ((uint32_t)l1 << 16);
            lv.y = (uint32_t)l2 | ((uint32_t)l3 << 16);
            uint32_t offh = (uint32_t)(la_row * 128 + kl * 2);
            uint32_t offl = offh + 64;
            *(uint2*)((char*)As + SWZ_A(offh)) = hv;
            *(uint2*)((char*)As + SWZ_A(offl)) = lv;
        }
        // ---- load B chunk: 32 x 128 fp32 -> split -> Bh/Bl ----
        {
            int gk = kt + lb_k;
            const float* Brow = B + (size_t)gk * N;
            bool kv = gk < K;
            #pragma unroll
            for (int q = 0; q < 4; q++) {
                int nl = lb_n0 + q * 4;
                int gn = n0 + nl;
                float4 v = make_float4(0.f, 0.f, 0.f, 0.f);
                if (kv) {
                    if (gn + 3 < N) v = *(const float4*)(Brow + gn);
                    else {
                        if (gn + 0 < N) v.x = Brow[gn + 0];
                        if (gn + 1 < N) v.y = Brow[gn + 1];
                        if (gn + 2 < N) v.z = Brow[gn + 2];
                        if (gn + 3 < N) v.w = Brow[gn + 3];
                    }
                }
                uint16_t h0, l0, h1, l1, h2, l2, h3, l3;
                bf16_split(v.x, h0, l0); bf16_split(v.y, h1, l1);
                bf16_split(v.z, h2, l2); bf16_split(v.w, h3, l3);
                uint2 hv, lv;
                hv.x = (uint32_t)h0 | ((uint32_t)h1 << 16);
                hv.y = (uint32_t)h2 | ((uint32_t)h3 << 16);
                lv.x = (uint32_t)l0 | ((uint32_t)l1 << 16);
                lv.y = (uint32_t)l2 | ((uint32_t)l3 << 16);
                uint32_t off = (uint32_t)(lb_k * 256 + nl * 2);
                *(uint2*)((char*)Bh + SWZ_B(off)) = hv;
                *(uint2*)((char*)Bl + SWZ_B(off)) = lv;
            }
        }
        __syncthreads();

        // ---- compute: 2 k16 steps, 3 bf16 passes each ----
        #pragma unroll
        for (int kc = 0; kc < 2; kc++) {
            uint32_t ah[4][4], al[4][4], bb[8];
            #pragma unroll
            for (int mi = 0; mi < 4; mi++) {
                uint32_t offh = (uint32_t)((wm * 64 + mi * 16 + (lane & 15)) * 128
                               + (kc * 16 + ((lane >> 4) << 3)) * 2);
                ldsm_x4(ah[mi], sA + SWZ_A(offh));
                uint32_t offl = offh + 64;
                ldsm_x4(al[mi], sA + SWZ_A(offl));
            }
            #pragma unroll
            for (int g = 0; g < 2; g++) {
                uint32_t off = (uint32_t)((kc * 16 + (lane & 15)) * 256
                              + (wn * 32 + g * 16 + ((lane & 16) ? 8 : 0)) * 2);
                ldsm_x4_t(&bb[4 * g], sBh + SWZ_B(off));
            }
            // Ah*Bh and Al*Bh
            #pragma unroll
            for (int mi = 0; mi < 4; mi++)
                #pragma unroll
                for (int ni = 0; ni < 4; ni++)
                    mma_bf16(d[mi][ni], ah[mi], bb[2 * ni], bb[2 * ni + 1]);
            #pragma unroll
            for (int mi = 0; mi < 4; mi++)
                #pragma unroll
                for (int ni = 0; ni < 4; ni++)
                    mma_bf16(d[mi][ni], al[mi], bb[2 * ni], bb[2 * ni + 1]);
            // Ah*Bl
            #pragma unroll
            for (int g = 0; g < 2; g++) {
                uint32_t off = (uint32_t)((kc * 16 + (lane & 15)) * 256
                              + (wn * 32 + g * 16 + ((lane & 16) ? 8 : 0)) * 2);
                ldsm_x4_t(&bb[4 * g], sBl + SWZ_B(off));
            }
            #pragma unroll
            for (int mi = 0; mi < 4; mi++)
                #pragma unroll
                for (int ni = 0; ni < 4; ni++)
                    mma_bf16(d[mi][ni], ah[mi], bb[2 * ni], bb[2 * ni + 1]);
        }
        __syncthreads();
    }

    // ---- epilogue: bias + store ----
    #pragma unroll
    for (int mi = 0; mi < 4; mi++) {
        int r0 = m0 + wm * 64 + mi * 16 + (lane >> 2);
        int r1 = r0 + 8;
        #pragma unroll
        for (int ni = 0; ni < 4; ni++) {
            int col = n0 + wn * 32 + ni * 8 + (lane & 3) * 2;
            if (col < N) {
                float b0 = bias[col], b1 = bias[col + 1];
                if (r0 < M) {
                    float2 o = make_float2(d[mi][ni][0] + b0, d[mi][ni][1] + b1);
                    *(float2*)(C + (size_t)r0 * N + col) = o;
                }
                if (r1 < M) {
                    float2 o = make_float2(d[mi][ni][2] + b0, d[mi][ni][3] + b1);
                    *(float2*)(C + (size_t)r1 * N + col) = o;
                }
            }
        }
    }
}

// ======================= column stats (sum, sumsq) =======================
__global__ void k_colstats(const float* __restrict__ C, int M, int N,
                           float* __restrict__ sum, float* __restrict__ sq) {
    int r0 = blockIdx.x * 512;
    int r1 = min(r0 + 512, M);
    float s[3] = {0.f, 0.f, 0.f}, q[3] = {0.f, 0.f, 0.f};
    for (int r = r0; r < r1; r++) {
        const float* row = C + (size_t)r * N;
        int j = 0;
        for (int c = threadIdx.x; c < N; c += 256, j++) {
            float v = row[c];
            s[j] += v;
            q[j] = fmaf(v, v, q[j]);
        }
    }
    int j = 0;
    for (int c = threadIdx.x; c < N; c += 256, j++) {
        atomicAdd(&sum[c], s[j]);
        atomicAdd(&sq[c], q[j]);
    }
}

// ======================= BN finalize =======================
__global__ void k_finalize(const float* __restrict__ sum, const float* __restrict__ sq,
                           const float* __restrict__ gam, const float* __restrict__ bet,
                           float* __restrict__ a, float* __restrict__ c, int n) {
    int i = blockIdx.x * blockDim.x + threadIdx.x;
    if (i < n) {
        float m   = sum[i] * (1.f / NN);
        float var = sq[i] * (1.f / NN) - m * m;
        float r   = rsqrtf(var + EPSV);
        float av  = gam[i] * r;
        a[i] = av;
        c[i] = bet[i] - m * av;
    }
}

// ======================= final output + pooling =======================
__global__ void k_output(const int* __restrict__ batch,
                         float* __restrict__ out_h, float* __restrict__ out_pool) {
    int idx = blockIdx.x * blockDim.x + threadIdx.x;
    if (idx < NN * HID) {
        int n = idx / HID;
        int f = idx - n * HID;
        float v = fmaf(g_a2[f], g_hraw[idx], g_c2[f]);
        out_h[idx] = v;
        atomicAdd(&out_pool[(size_t)batch[n] * HID + f], v);
    }
}

// ======================= host driver =======================
extern "C" void kernel_launch(void* const* d_in, const int* in_sizes, int n_in,
                              void* d_out, int out_size) {
    const int*   batch = (const int*)  d_in[0];
    const float* x     = (const float*)d_in[1];
    const int*   ei    = (const int*)  d_in[2];
    const float* ea    = (const float*)d_in[3];
    const float* linW  = (const float*)d_in[4];
    const float* linb  = (const float*)d_in[5];
    const float* W1s   = (const float*)d_in[6];
    const float* b1s   = (const float*)d_in[7];
    const float* g1s   = (const float*)d_in[8];
    const float* be1s  = (const float*)d_in[9];
    const float* W2s   = (const float*)d_in[10];
    const float* b2s   = (const float*)d_in[11];
    const float* gos   = (const float*)d_in[12];
    const float* bos   = (const float*)d_in[13];

    float* out      = (float*)d_out;
    float* out_h    = out;
    float* out_pool = out + (size_t)NN * HID;

    const int* src = ei;
    const int* dst = ei + NE;

    float *p_hraw, *p_agg, *p_t;
    float *p_sum1, *p_sq1, *p_a1, *p_c1, *p_sum2, *p_sq2, *p_a2, *p_c2;
    cudaGetSymbolAddress((void**)&p_hraw, g_hraw);
    cudaGetSymbolAddress((void**)&p_agg,  g_agg);
    cudaGetSymbolAddress((void**)&p_t,    g_t);
    cudaGetSymbolAddress((void**)&p_sum1, g_sum1);
    cudaGetSymbolAddress((void**)&p_sq1,  g_sq1);
    cudaGetSymbolAddress((void**)&p_a1,   g_a1);
    cudaGetSymbolAddress((void**)&p_c1,   g_c1);
    cudaGetSymbolAddress((void**)&p_sum2, g_sum2);
    cudaGetSymbolAddress((void**)&p_sq2,  g_sq2);
    cudaGetSymbolAddress((void**)&p_a2,   g_a2);
    cudaGetSymbolAddress((void**)&p_c2,   g_c2);

    const int EB = (NE + 255) / 256;

    // ---- CSR build ----
    k_zero_deg<<<(NN + 255) / 256, 256>>>();
    k_count<<<EB, 256>>>(dst);
    k_scan<<<1, 1024>>>();
    k_scatter<<<EB, 256>>>(src, dst, ea);

    // ---- h0 = x @ linW + linb (K=20, SIMT) ----
    {
        dim3 grid((HID + 127) / 128, (NN + 127) / 128);
        k_gemm0<<<grid, 256>>>(x, linW, linb, p_hraw, NN, HID, 20);
    }

    dim3 grid1((HID2 + 127) / 128, (NN + 127) / 128);  // 5 x 391
    dim3 grid2((HID  + 127) / 128, (NN + 127) / 128);  // 3 x 391
    const int SB = (NN + 511) / 512;

    for (int i = 0; i < NLAYER; i++) {
        // message passing (prev-layer BN+relu fused into gather)
        if (i == 0)
            k_spmm<false><<<NN, 320>>>(p_hraw, nullptr, nullptr);
        else
            k_spmm<true><<<NN, 320>>>(p_hraw, p_a2, p_c2);

        // GEMM1: t = agg @ W1 + b1   (mma.sync bf16 split-2)
        k_tgemm<false><<<grid1, 256>>>(p_agg, W1s + (size_t)i * HID * HID2,
                                       b1s + (size_t)i * HID2, nullptr, nullptr,
                                       p_t, NN, HID2, HID);
        k_zero_f<<<(HID2 + 255) / 256, 256>>>(p_sum1, HID2);
        k_zero_f<<<(HID2 + 255) / 256, 256>>>(p_sq1, HID2);
        k_colstats<<<SB, 256>>>(p_t, NN, HID2, p_sum1, p_sq1);
        k_finalize<<<(HID2 + 255) / 256, 256>>>(p_sum1, p_sq1,
                                                g1s + (size_t)i * HID2, be1s + (size_t)i * HID2,
                                                p_a1, p_c1, HID2);

        // GEMM2: h = relu(bn1(t)) @ W2 + b2  (transform fused into A-loader)
        k_tgemm<true><<<grid2, 256>>>(p_t, W2s + (size_t)i * HID2 * HID,
                                      b2s + (size_t)i * HID, p_a1, p_c1,
                                      p_hraw, NN, HID, HID2);
        k_zero_f<<<(HID + 255) / 256, 256>>>(p_sum2, HID);
        k_zero_f<<<(HID + 255) / 256, 256>>>(p_sq2, HID);
        k_colstats<<<SB, 256>>>(p_hraw, NN, HID, p_sum2, p_sq2);
        k_finalize<<<(HID + 255) / 256, 256>>>(p_sum2, p_sq2,
                                               gos + (size_t)i * HID, bos + (size_t)i * HID,
                                               p_a2, p_c2, HID);
    }

    // ---- output: h (bn, no relu) and xpool ----
    k_zero_f<<<(NG * HID + 255) / 256, 256>>>(out_pool, NG * HID);
    k_output<<<((NN * HID) + 255) / 256, 256>>>(batch, out_h, out_pool);
}

// round 7
// speedup vs baseline: 1.6608x; 1.6608x over previous
#include <cuda_runtime.h>
#include <cstdint>

#define NN 50000
#define NE 800000
#define NG 64
#define HID 300
#define HID2 600
#define NLAYER 5
#define EPSV 1e-5f

// ---------------- scratch (static __device__, no allocs) ----------------
__device__ float g_hraw[(size_t)NN * HID];
__device__ float g_agg [(size_t)NN * HID];
__device__ float g_t   [(size_t)NN * HID2];
__device__ int   g_deg [NN];
__device__ int   g_rowptr[NN + 1];
__device__ int   g_cursor[NN];
__device__ int   g_srcs[NE];
__device__ float g_ews [NE];
__device__ float g_sum1[HID2], g_sq1[HID2], g_a1[HID2], g_c1[HID2];
__device__ float g_sum2[HID],  g_sq2[HID],  g_a2[HID],  g_c2[HID];

// ---------------- packed f32x2 helpers ----------------
__device__ __forceinline__ void ffma2(unsigned long long& d,
                                      unsigned long long a, unsigned long long b) {
    asm("fma.rn.f32x2 %0, %1, %2, %0;" : "+l"(d) : "l"(a), "l"(b));
}
__device__ __forceinline__ unsigned long long dup_f32(float v) {
    unsigned long long r;
    asm("mov.b64 %0, {%1, %1};" : "=l"(r) : "r"(__float_as_uint(v)));
    return r;
}
__device__ __forceinline__ void unpack2(unsigned long long p, float& lo, float& hi) {
    uint32_t l, h;
    asm("mov.b64 {%0, %1}, %2;" : "=r"(l), "=r"(h) : "l"(p));
    lo = __uint_as_float(l);
    hi = __uint_as_float(h);
}

// ---------------- small utility kernels ----------------
__global__ void k_zero_f(float* p, int n) {
    int i = blockIdx.x * blockDim.x + threadIdx.x;
    if (i < n) p[i] = 0.f;
}
__global__ void k_zero_deg() {
    int i = blockIdx.x * blockDim.x + threadIdx.x;
    if (i < NN) g_deg[i] = 0;
}
__global__ void k_count(const int* __restrict__ dst) {
    int e = blockIdx.x * blockDim.x + threadIdx.x;
    if (e < NE) atomicAdd(&g_deg[dst[e]], 1);
}
// single-block exclusive scan of g_deg -> g_rowptr, g_cursor
__global__ void k_scan() {
    __shared__ int sh[1024];
    int offset = 0;
    for (int base = 0; base < NN; base += 1024) {
        int i = base + threadIdx.x;
        int v = (i < NN) ? g_deg[i] : 0;
        sh[threadIdx.x] = v;
        __syncthreads();
        #pragma unroll
        for (int d = 1; d < 1024; d <<= 1) {
            int t = (threadIdx.x >= d) ? sh[threadIdx.x - d] : 0;
            __syncthreads();
            sh[threadIdx.x] += t;
            __syncthreads();
        }
        int incl = sh[threadIdx.x];
        if (i < NN) {
            g_rowptr[i] = offset + incl - v;
            g_cursor[i] = offset + incl - v;
        }
        offset += sh[1023];
        __syncthreads();
    }
    if (threadIdx.x == 0) g_rowptr[NN] = offset;
}
__global__ void k_scatter(const int* __restrict__ src, const int* __restrict__ dst,
                          const float* __restrict__ ea) {
    int e = blockIdx.x * blockDim.x + threadIdx.x;
    if (e < NE) {
        int d = dst[e];
        int p = atomicAdd(&g_cursor[d], 1);
        g_srcs[p] = src[e];
        g_ews[p]  = ea[e];
    }
}

// ---------------- SpMM: agg[n] = sum_e ew * f(h[src]) ----------------
template <bool TRANS>
__global__ void k_spmm(const float* __restrict__ hraw,
                       const float* __restrict__ a, const float* __restrict__ c) {
    int n = blockIdx.x;
    int f = threadIdx.x;
    int beg = g_rowptr[n], end = g_rowptr[n + 1];
    if (f >= HID) return;
    float af = 0.f, cf = 0.f;
    if (TRANS) { af = a[f]; cf = c[f]; }
    float acc = 0.f;
    for (int e = beg; e < end; e++) {
        int s  = g_srcs[e];
        float w = g_ews[e];
        float v = __ldg(hraw + (size_t)s * HID + f);
        if (TRANS) v = fmaxf(fmaf(af, v, cf), 0.f);
        acc = fmaf(w, v, acc);
    }
    g_agg[(size_t)n * HID + f] = acc;
}

// ---------------- tiled fp32 GEMM with packed FFMA2 core ----------------
// C = f(A) @ B + bias, fused BN stats.
// A: [M,K] row-major, B: [K,N] row-major.
// TRANS_A: f(v) = relu(ta[k]*v + tc[k]); else identity.
// STATS: accumulate per-column sum / sumsq of C (rows < M only).
#define BM 128
#define BN 128
#define BK 8
template <bool TRANS_A, bool STATS>
__global__ __launch_bounds__(256, 2)
void k_gemm(const float* __restrict__ A, const float* __restrict__ B,
            const float* __restrict__ bias,
            const float* __restrict__ ta, const float* __restrict__ tc,
            float* __restrict__ C, int M, int N, int K,
            float* __restrict__ sum_out, float* __restrict__ sq_out) {
    __shared__ float As[BK][BM + 4];   // row stride 132 floats = 528B (8B-aligned)
    __shared__ float Bs[BK][BN];
    __shared__ float red[16][BN];

    int tid = threadIdx.x;
    int tx = tid & 15, ty = tid >> 4;
    int m0 = blockIdx.y * BM, n0 = blockIdx.x * BN;

    int arow = tid >> 1;          // 0..127
    int ak   = (tid & 1) * 4;     // 0 or 4
    int bk   = tid >> 5;          // 0..7
    int bn   = (tid & 31) * 4;    // 0..124

    // packed accumulators: acc2[i2][j] holds rows (ty*8+2*i2, +1), col tx*8+j
    unsigned long long acc2[4][8];
    #pragma unroll
    for (int i = 0; i < 4; i++)
        #pragma unroll
        for (int j = 0; j < 8; j++) acc2[i][j] = 0ull;

    for (int k0 = 0; k0 < K; k0 += BK) {
        float4 av = make_float4(0.f, 0.f, 0.f, 0.f);
        if (m0 + arow < M && k0 + ak < K) {
            av = *(const float4*)(A + (size_t)(m0 + arow) * K + k0 + ak);
            if (TRANS_A) {
                float4 a4 = *(const float4*)(ta + k0 + ak);
                float4 c4 = *(const float4*)(tc + k0 + ak);
                av.x = fmaxf(fmaf(a4.x, av.x, c4.x), 0.f);
                av.y = fmaxf(fmaf(a4.y, av.y, c4.y), 0.f);
                av.z = fmaxf(fmaf(a4.z, av.z, c4.z), 0.f);
                av.w = fmaxf(fmaf(a4.w, av.w, c4.w), 0.f);
            }
        }
        As[ak + 0][arow] = av.x;
        As[ak + 1][arow] = av.y;
        As[ak + 2][arow] = av.z;
        As[ak + 3][arow] = av.w;

        float4 bv4 = make_float4(0.f, 0.f, 0.f, 0.f);
        if (k0 + bk < K && n0 + bn < N)
            bv4 = *(const float4*)(B + (size_t)(k0 + bk) * N + n0 + bn);
        *(float4*)&Bs[bk][bn] = bv4;

        __syncthreads();
        #pragma unroll
        for (int kk = 0; kk < BK; kk++) {
            // a pairs: As[kk][ty*8 + 2i .. 2i+1]  (8B-aligned LDS.64)
            unsigned long long a2[4];
            #pragma unroll
            for (int i = 0; i < 4; i++)
                a2[i] = *(const unsigned long long*)&As[kk][ty * 8 + 2 * i];
            // b duplicated pairs
            unsigned long long bd[8];
            #pragma unroll
            for (int j = 0; j < 8; j++)
                bd[j] = dup_f32(Bs[kk][tx * 8 + j]);
            #pragma unroll
            for (int i = 0; i < 4; i++)
                #pragma unroll
                for (int j = 0; j < 8; j++)
                    ffma2(acc2[i][j], a2[i], bd[j]);
        }
        __syncthreads();
    }

    // bias
    float bv[8];
    #pragma unroll
    for (int j = 0; j < 8; j++) {
        int col = n0 + tx * 8 + j;
        bv[j] = (col < N) ? bias[col] : 0.f;
    }

    float s[8], q[8];
    #pragma unroll
    for (int j = 0; j < 8; j++) { s[j] = 0.f; q[j] = 0.f; }

    // unpack per M-pair: bias, store, stats
    #pragma unroll
    for (int i2 = 0; i2 < 4; i2++) {
        float lo[8], hi[8];
        #pragma unroll
        for (int j = 0; j < 8; j++) {
            unpack2(acc2[i2][j], lo[j], hi[j]);
            lo[j] += bv[j];
            hi[j] += bv[j];
        }
        int r0 = m0 + ty * 8 + 2 * i2;
        int r1 = r0 + 1;
        int colb = n0 + tx * 8;
        if (r0 < M) {
            if (colb < N)
                *(float4*)(C + (size_t)r0 * N + colb) =
                    make_float4(lo[0], lo[1], lo[2], lo[3]);
            if (colb + 4 < N)
                *(float4*)(C + (size_t)r0 * N + colb + 4) =
                    make_float4(lo[4], lo[5], lo[6], lo[7]);
            if (STATS)
                #pragma unroll
                for (int j = 0; j < 8; j++) {
                    s[j] += lo[j];
                    q[j] = fmaf(lo[j], lo[j], q[j]);
                }
        }
        if (r1 < M) {
            if (colb < N)
                *(float4*)(C + (size_t)r1 * N + colb) =
                    make_float4(hi[0], hi[1], hi[2], hi[3]);
            if (colb + 4 < N)
                *(float4*)(C + (size_t)r1 * N + colb + 4) =
                    make_float4(hi[4], hi[5], hi[6], hi[7]);
            if (STATS)
                #pragma unroll
                for (int j = 0; j < 8; j++) {
                    s[j] += hi[j];
                    q[j] = fmaf(hi[j], hi[j], q[j]);
                }
        }
    }

    if (STATS) {
        #pragma unroll
        for (int j = 0; j < 8; j++) red[ty][tx * 8 + j] = s[j];
        __syncthreads();
        if (tid < BN) {
            float t = 0.f;
            #pragma unroll
            for (int r = 0; r < 16; r++) t += red[r][tid];
            int col = n0 + tid;
            if (col < N) atomicAdd(&sum_out[col], t);
        }
        __syncthreads();
        #pragma unroll
        for (int j = 0; j < 8; j++) red[ty][tx * 8 + j] = q[j];
        __syncthreads();
        if (tid < BN) {
            float t = 0.f;
            #pragma unroll
            for (int r = 0; r < 16; r++) t += red[r][tid];
            int col = n0 + tid;
            if (col < N) atomicAdd(&sq_out[col], t);
        }
    }
}

// ---------------- BN finalize: a = g*rstd, c = beta - mean*a ----------------
__global__ void k_finalize(const float* __restrict__ sum, const float* __restrict__ sq,
                           const float* __restrict__ gam, const float* __restrict__ bet,
                           float* __restrict__ a, float* __restrict__ c, int n) {
    int i = blockIdx.x * blockDim.x + threadIdx.x;
    if (i < n) {
        float m   = sum[i] * (1.f / NN);
        float var = sq[i] * (1.f / NN) - m * m;
        float r   = rsqrtf(var + EPSV);
        float av  = gam[i] * r;
        a[i] = av;
        c[i] = bet[i] - m * av;
    }
}

// ---------------- final output: h = a2*hraw + c2 (no relu), pool by batch ----------------
__global__ void k_output(const int* __restrict__ batch,
                         float* __restrict__ out_h, float* __restrict__ out_pool) {
    int idx = blockIdx.x * blockDim.x + threadIdx.x;
    if (idx < NN * HID) {
        int n = idx / HID;
        int f = idx - n * HID;
        float v = fmaf(g_a2[f], g_hraw[idx], g_c2[f]);
        out_h[idx] = v;
        atomicAdd(&out_pool[(size_t)batch[n] * HID + f], v);
    }
}

// ---------------- host driver ----------------
extern "C" void kernel_launch(void* const* d_in, const int* in_sizes, int n_in,
                              void* d_out, int out_size) {
    const int*   batch = (const int*)  d_in[0];
    const float* x     = (const float*)d_in[1];
    const int*   ei    = (const int*)  d_in[2];   // [2, NE]: src then dst
    const float* ea    = (const float*)d_in[3];
    const float* linW  = (const float*)d_in[4];
    const float* linb  = (const float*)d_in[5];
    const float* W1s   = (const float*)d_in[6];
    const float* b1s   = (const float*)d_in[7];
    const float* g1s   = (const float*)d_in[8];
    const float* be1s  = (const float*)d_in[9];
    const float* W2s   = (const float*)d_in[10];
    const float* b2s   = (const float*)d_in[11];
    const float* gos   = (const float*)d_in[12];
    const float* bos   = (const float*)d_in[13];

    float* out      = (float*)d_out;
    float* out_h    = out;
    float* out_pool = out + (size_t)NN * HID;

    const int* src = ei;
    const int* dst = ei + NE;

    float *p_hraw, *p_agg, *p_t;
    float *p_sum1, *p_sq1, *p_a1, *p_c1, *p_sum2, *p_sq2, *p_a2, *p_c2;
    cudaGetSymbolAddress((void**)&p_hraw, g_hraw);
    cudaGetSymbolAddress((void**)&p_agg,  g_agg);
    cudaGetSymbolAddress((void**)&p_t,    g_t);
    cudaGetSymbolAddress((void**)&p_sum1, g_sum1);
    cudaGetSymbolAddress((void**)&p_sq1,  g_sq1);
    cudaGetSymbolAddress((void**)&p_a1,   g_a1);
    cudaGetSymbolAddress((void**)&p_c1,   g_c1);
    cudaGetSymbolAddress((void**)&p_sum2, g_sum2);
    cudaGetSymbolAddress((void**)&p_sq2,  g_sq2);
    cudaGetSymbolAddress((void**)&p_a2,   g_a2);
    cudaGetSymbolAddress((void**)&p_c2,   g_c2);

    const int EB = (NE + 255) / 256;

    // ---- CSR build ----
    k_zero_deg<<<(NN + 255) / 256, 256>>>();
    k_count<<<EB, 256>>>(dst);
    k_scan<<<1, 1024>>>();
    k_scatter<<<EB, 256>>>(src, dst, ea);

    // ---- h0 = x @ linW + linb ----
    {
        dim3 grid((HID + BN - 1) / BN, (NN + BM - 1) / BM);
        k_gemm<false, false><<<grid, 256>>>(x, linW, linb, nullptr, nullptr,
                                            p_hraw, NN, HID, 2 * 10, nullptr, nullptr);
    }

    dim3 grid1((HID2 + BN - 1) / BN, (NN + BM - 1) / BM);  // 5 x 391
    dim3 grid2((HID  + BN - 1) / BN, (NN + BM - 1) / BM);  // 3 x 391

    for (int i = 0; i < NLAYER; i++) {
        // message passing + segment sum (input transform = previous layer BN+relu)
        if (i == 0)
            k_spmm<false><<<NN, 320>>>(p_hraw, nullptr, nullptr);
        else
            k_spmm<true><<<NN, 320>>>(p_hraw, p_a2, p_c2);

        // GEMM1 + fused stats
        k_zero_f<<<(HID2 + 255) / 256, 256>>>(p_sum1, HID2);
        k_zero_f<<<(HID2 + 255) / 256, 256>>>(p_sq1, HID2);
        k_gemm<false, true><<<grid1, 256>>>(p_agg, W1s + (size_t)i * HID * HID2,
                                            b1s + (size_t)i * HID2, nullptr, nullptr,
                                            p_t, NN, HID2, HID, p_sum1, p_sq1);
        k_finalize<<<(HID2 + 255) / 256, 256>>>(p_sum1, p_sq1,
                                                g1s + (size_t)i * HID2, be1s + (size_t)i * HID2,
                                                p_a1, p_c1, HID2);

        // GEMM2 with fused relu(bn1) on A-load, + fused stats
        k_zero_f<<<(HID + 255) / 256, 256>>>(p_sum2, HID);
        k_zero_f<<<(HID + 255) / 256, 256>>>(p_sq2, HID);
        k_gemm<true, true><<<grid2, 256>>>(p_t, W2s + (size_t)i * HID2 * HID,
                                           b2s + (size_t)i * HID, p_a1, p_c1,
                                           p_hraw, NN, HID, HID2, p_sum2, p_sq2);
        k_finalize<<<(HID + 255) / 256, 256>>>(p_sum2, p_sq2,
                                               gos + (size_t)i * HID, bos + (size_t)i * HID,
                                               p_a2, p_c2, HID);
    }

    // ---- output: h (bn, no relu) and xpool ----
    k_zero_f<<<(NG * HID + 255) / 256, 256>>>(out_pool, NG * HID);
    k_output<<<((NN * HID) + 255) / 256, 256>>>(batch, out_h, out_pool);
}